// round 17
// baseline (speedup 1.0000x reference)
#include <cuda_runtime.h>
#include <cstdint>

#define B_    32
#define IC_   16
#define OC_   16
#define KTOT  65536      // (M-1)*(N-1)
#define E_    131584     // edges
#define VOFF  65792      // M*(N-1)
#define KT    32         // k per tile (never crosses a 256-wide row)
#define NBUF  6          // weight pipeline depth (6 x 4KB = 24KB smem/CTA)
#define LOOKA 5          // issue lookahead (stage ic+5)
#define BSTR  ((size_t)IC_ * E_)   // x stride per batch (floats)

__device__ __forceinline__ void cp_async16(unsigned dst, const void* src) {
    asm volatile("cp.async.cg.shared.global [%0], [%1], 16;\n"
                 :: "r"(dst), "l"(src) : "memory");
}
__device__ __forceinline__ void cp_commit() {
    asm volatile("cp.async.commit_group;\n" ::: "memory");
}
template<int N>
__device__ __forceinline__ void cp_wait() {
    asm volatile("cp.async.wait_group %0;\n" :: "n"(N) : "memory");
}
// volatile + memory clobber: must NOT be hoisted above cp_wait/__syncthreads
__device__ __forceinline__ float4 lds128(unsigned sa) {
    float4 w;
    asm volatile("ld.shared.v4.f32 {%0, %1, %2, %3}, [%4];"
                 : "=f"(w.x), "=f"(w.y), "=f"(w.z), "=f"(w.w)
                 : "r"(sa) : "memory");
    return w;
}

// CTA: 32 k-lanes x 8 warps (bg), 256 threads, 4 CTAs/SM (32 warps).
// CTA owns one oh-half (8 o) x all 32 batches x one 32-wide k-tile.
// o-ranges disjoint across the 2 CTAs of a tile => weights stream from DRAM
// exactly once. Fully-unrolled ic loop: waits/buffers/addresses fold to
// compile-time immediates; LDS loads pinned after barriers via volatile asm.
__global__ __launch_bounds__(256, 4)
void edges_kernel(const float* __restrict__ x,
                  const float4* __restrict__ w4,
                  const float* __restrict__ bias,
                  float* __restrict__ out)
{
    __shared__ float4 sw[NBUF][8 * KT];   // [buf][olocal*32 + klocal], 4 KB/buf

    const int lane = threadIdx.x;
    const int bg   = threadIdx.y;          // 0..7
    const int bbase = bg * 4;

    const int oh   = blockIdx.x & 1;
    const int tile = blockIdx.x >> 1;

    const int k0 = tile * KT;
    const int k  = k0 + lane;
    const int i  = k0 >> 8;
    const int c0 = k;                                   // t0; t1 = c0+256
    const int c2 = VOFF + i * 257 + (k0 & 255) + lane;  // t2; t3 = c2+1

    // cooperative weight copy: 256 threads x 16B = one 4 KB slab per ic
    const int tld = bg * 32 + lane;
    const float4* wsrc = w4
        + (size_t)((oh * 8 + (tld >> 5)) * IC_) * KTOT + k0 + (tld & 31);
    const unsigned swdst0 = (unsigned)__cvta_generic_to_shared(&sw[0][tld]);

    const float* xbase = x + (size_t)bbase * BSTR;

    // bias folded into accumulator init
    float acc[8][4];
    #pragma unroll
    for (int oo = 0; oo < 8; ++oo) {
        const float bo = __ldg(&bias[oh * 8 + oo]);
        #pragma unroll
        for (int bb = 0; bb < 4; ++bb) acc[oo][bb] = bo;
    }

    // prologue: weight stages 0..LOOKA-1
    #pragma unroll
    for (int s = 0; s < LOOKA; ++s) {
        cp_async16(swdst0 + (s % NBUF) * (8 * KT * 16), wsrc + (size_t)s * KTOT);
        cp_commit();
    }

    #pragma unroll
    for (int ic = 0; ic < IC_; ++ic) {
        // x gather for this ic FIRST: overlaps the cp-wait + barrier below
        float xf[4][4];
        {
            const float* p = xbase + (size_t)ic * E_;
            #pragma unroll
            for (int bb = 0; bb < 4; ++bb) {
                const float* xb = p + (size_t)bb * BSTR;
                xf[bb][0] = __ldg(xb + c0);
                xf[bb][1] = __ldg(xb + c0 + 256);
                xf[bb][2] = __ldg(xb + c2);
                xf[bb][3] = __ldg(xb + c2 + 1);
            }
        }

        // wait for weight stage ic (compile-time constant under full unroll)
        if (ic <= IC_ - 1 - LOOKA)   cp_wait<LOOKA - 1>();
        else if (ic == IC_ - 4)      cp_wait<3>();
        else if (ic == IC_ - 3)      cp_wait<2>();
        else if (ic == IC_ - 2)      cp_wait<1>();
        else                         cp_wait<0>();
        __syncthreads();

        // issue stage ic+LOOKA (reuses buffer freed by stage ic-1)
        if (ic + LOOKA < IC_) {
            cp_async16(swdst0 + ((ic + LOOKA) % NBUF) * (8 * KT * 16),
                       wsrc + (size_t)(ic + LOOKA) * KTOT);
            cp_commit();
        }

        // compute: 8 o x 4 b x 4 t scalar FFMA
        const unsigned sa = (unsigned)__cvta_generic_to_shared(
                                &sw[ic % NBUF][lane]);
        #pragma unroll
        for (int oo = 0; oo < 8; ++oo) {
            const float4 w = lds128(sa + oo * (KT * 16));
            #pragma unroll
            for (int bb = 0; bb < 4; ++bb) {
                acc[oo][bb] += w.x * xf[bb][0];
                acc[oo][bb] += w.y * xf[bb][1];
                acc[oo][bb] += w.z * xf[bb][2];
                acc[oo][bb] += w.w * xf[bb][3];
            }
        }
    }

    // epilogue: coalesced STG.32 (bias already included)
    #pragma unroll
    for (int oo = 0; oo < 8; ++oo) {
        const int o = oh * 8 + oo;
        #pragma unroll
        for (int bb = 0; bb < 4; ++bb)
            out[(size_t)((bbase + bb) * OC_ + o) * KTOT + k] = acc[oo][bb];
    }
}

extern "C" void kernel_launch(void* const* d_in, const int* in_sizes, int n_in,
                              void* d_out, int out_size)
{
    const float*  x    = (const float*)d_in[0];
    const float4* w4   = (const float4*)d_in[1];
    const float*  bias = (const float*)d_in[2];
    float*        out  = (float*)d_out;

    dim3 block(32, 8);
    dim3 grid((KTOT / KT) * 2);   // 4096 CTAs: (tile, oh-half)
    edges_kernel<<<grid, block>>>(x, w4, bias, out);
}